// round 7
// baseline (speedup 1.0000x reference)
#include <cuda_runtime.h>

// x: (2,1,128,128,128) f32; vectors: (10,12) f32
// out: (2, 768, 32, 32, 32) f32, o = ((pd*4+ph)*4+pw)*12 + v
// bin = searchsorted(HU_EDGES, x, 'right') = sum(x >= edge_i)
//
// grid = 2048 blocks (b,gd,gh), block = 512 threads (pd,ph,pw,gw4).
// Each thread: 4 scalar LDG -> 4 bins -> 12 coalesced float4 stores.
// All indices 32-bit (out = 12.58M float4s, x = 4.2M floats).

__device__ __forceinline__ int bin1(float f)
{
    return (f >= -1000.0f) + (f >= -75.0f) + (f >= 0.0f)
         + (f >= 15.0f)    + (f >= 25.0f)  + (f >= 40.0f)
         + (f >= 50.0f)    + (f >= 200.0f) + (f >= 1000.0f);
}

__global__ __launch_bounds__(512, 3) void lcv_kernel(
    const float* __restrict__ x,
    const float* __restrict__ vectors,
    float* __restrict__ out)
{
    __shared__ float vs[120];          // 10 bins x 12 dims
    const int tid = threadIdx.x;
    if (tid < 120) vs[tid] = vectors[tid];
    __syncthreads();

    const int gw4 = tid & 7;
    const int pw  = (tid >> 3) & 3;
    const int ph  = (tid >> 5) & 3;
    const int pd  = tid >> 7;

    const int bi = blockIdx.x;
    const int gh = bi & 31;
    const int gd = (bi >> 5) & 31;
    const int b  = bi >> 10;

    // voxels this thread needs: w = gw4*16 + 4k + pw, k = 0..3
    const int xoff = (((b * 128 + (gd * 4 + pd)) * 128
                      + (gh * 4 + ph)) * 128) + gw4 * 16 + pw;
    const float* xr = x + xoff;
    const float* p0 = vs + bin1(__ldg(xr + 0))  * 12;
    const float* p1 = vs + bin1(__ldg(xr + 4))  * 12;
    const float* p2 = vs + bin1(__ldg(xr + 8))  * 12;
    const float* p3 = vs + bin1(__ldg(xr + 12)) * 12;

    float4* out4 = reinterpret_cast<float4*>(out);
    const int p = (pd * 4 + ph) * 4 + pw;
    // float4-unit offset; max = 2*768*8192 = 12.58M, fits in int
    const int obase = (b * 768 + p * 12) * 8192 + (gd * 32 + gh) * 8 + gw4;

    #pragma unroll
    for (int v = 0; v < 12; v++) {
        float4 r;
        r.x = p0[v]; r.y = p1[v]; r.z = p2[v]; r.w = p3[v];
        __stcs(&out4[obase + v * 8192], r);
    }
}

extern "C" void kernel_launch(void* const* d_in, const int* in_sizes, int n_in,
                              void* d_out, int out_size)
{
    const float* x       = (const float*)d_in[0];
    const float* vectors = (const float*)d_in[1];
    float* out           = (float*)d_out;
    lcv_kernel<<<2048, 512>>>(x, vectors, out);
}

// round 8
// speedup vs baseline: 1.0193x; 1.0193x over previous
#include <cuda_runtime.h>

// x: (2,1,128,128,128) f32; vectors: (10,12) f32
// out: (2, 768, 32, 32, 32) f32, o = ((pd*4+ph)*4+pw)*12 + v
// bin = searchsorted(HU_EDGES, x, 'right') = sum(x >= edge_i)
//
// grid = 2048 blocks (b,gd,gh), block = 512 threads (pd,ph,pw,gw4).
// Each thread: 4 scalar LDG -> 4 bins -> 12 coalesced float4 stores.
// All indices 32-bit (out = 12.58M float4s, x = 4.2M floats).

__device__ __forceinline__ int bin1(float f)
{
    return (f >= -1000.0f) + (f >= -75.0f) + (f >= 0.0f)
         + (f >= 15.0f)    + (f >= 25.0f)  + (f >= 40.0f)
         + (f >= 50.0f)    + (f >= 200.0f) + (f >= 1000.0f);
}

__global__ __launch_bounds__(512, 3) void lcv_kernel(
    const float* __restrict__ x,
    const float* __restrict__ vectors,
    float* __restrict__ out)
{
    __shared__ float vs[120];          // 10 bins x 12 dims
    const int tid = threadIdx.x;
    if (tid < 120) vs[tid] = vectors[tid];
    __syncthreads();

    const int gw4 = tid & 7;
    const int pw  = (tid >> 3) & 3;
    const int ph  = (tid >> 5) & 3;
    const int pd  = tid >> 7;

    const int bi = blockIdx.x;
    const int gh = bi & 31;
    const int gd = (bi >> 5) & 31;
    const int b  = bi >> 10;

    // voxels this thread needs: w = gw4*16 + 4k + pw, k = 0..3
    const int xoff = (((b * 128 + (gd * 4 + pd)) * 128
                      + (gh * 4 + ph)) * 128) + gw4 * 16 + pw;
    const float* xr = x + xoff;
    const float* p0 = vs + bin1(__ldg(xr + 0))  * 12;
    const float* p1 = vs + bin1(__ldg(xr + 4))  * 12;
    const float* p2 = vs + bin1(__ldg(xr + 8))  * 12;
    const float* p3 = vs + bin1(__ldg(xr + 12)) * 12;

    float4* out4 = reinterpret_cast<float4*>(out);
    const int p = (pd * 4 + ph) * 4 + pw;
    // float4-unit offset; max = 2*768*8192 = 12.58M, fits in int
    const int obase = (b * 768 + p * 12) * 8192 + (gd * 32 + gh) * 8 + gw4;

    #pragma unroll
    for (int v = 0; v < 12; v++) {
        float4 r;
        r.x = p0[v]; r.y = p1[v]; r.z = p2[v]; r.w = p3[v];
        __stcs(&out4[obase + v * 8192], r);
    }
}

extern "C" void kernel_launch(void* const* d_in, const int* in_sizes, int n_in,
                              void* d_out, int out_size)
{
    const float* x       = (const float*)d_in[0];
    const float* vectors = (const float*)d_in[1];
    float* out           = (float*)d_out;
    lcv_kernel<<<2048, 512>>>(x, vectors, out);
}

// round 11
// speedup vs baseline: 1.0306x; 1.0111x over previous
#include <cuda_runtime.h>

// x: (2,1,128,128,128) f32; vectors: (10,12) f32
// out: (2, 768, 32, 32, 32) f32, o = ((pd*4+ph)*4+pw)*12 + v
// bin = searchsorted(HU_EDGES, x, 'right') = sum(x >= edge_i)
//
// grid = 2048 blocks (b,gd,gh), block = 512 threads (pd,ph,pw,gw4).
// Each thread: 4 scalar LDG -> 4 bins -> 12 coalesced float4 stores.
// All indices 32-bit (out = 12.58M float4s, x = 4.2M floats).

__device__ __forceinline__ int bin1(float f)
{
    return (f >= -1000.0f) + (f >= -75.0f) + (f >= 0.0f)
         + (f >= 15.0f)    + (f >= 25.0f)  + (f >= 40.0f)
         + (f >= 50.0f)    + (f >= 200.0f) + (f >= 1000.0f);
}

__global__ __launch_bounds__(512, 3) void lcv_kernel(
    const float* __restrict__ x,
    const float* __restrict__ vectors,
    float* __restrict__ out)
{
    __shared__ float vs[120];          // 10 bins x 12 dims
    const int tid = threadIdx.x;
    if (tid < 120) vs[tid] = vectors[tid];
    __syncthreads();

    const int gw4 = tid & 7;
    const int pw  = (tid >> 3) & 3;
    const int ph  = (tid >> 5) & 3;
    const int pd  = tid >> 7;

    const int bi = blockIdx.x;
    const int gh = bi & 31;
    const int gd = (bi >> 5) & 31;
    const int b  = bi >> 10;

    // voxels this thread needs: w = gw4*16 + 4k + pw, k = 0..3
    const int xoff = (((b * 128 + (gd * 4 + pd)) * 128
                      + (gh * 4 + ph)) * 128) + gw4 * 16 + pw;
    const float* xr = x + xoff;
    const float* p0 = vs + bin1(__ldg(xr + 0))  * 12;
    const float* p1 = vs + bin1(__ldg(xr + 4))  * 12;
    const float* p2 = vs + bin1(__ldg(xr + 8))  * 12;
    const float* p3 = vs + bin1(__ldg(xr + 12)) * 12;

    float4* out4 = reinterpret_cast<float4*>(out);
    const int p = (pd * 4 + ph) * 4 + pw;
    // float4-unit offset; max = 2*768*8192 = 12.58M, fits in int
    const int obase = (b * 768 + p * 12) * 8192 + (gd * 32 + gh) * 8 + gw4;

    #pragma unroll
    for (int v = 0; v < 12; v++) {
        float4 r;
        r.x = p0[v]; r.y = p1[v]; r.z = p2[v]; r.w = p3[v];
        __stcs(&out4[obase + v * 8192], r);
    }
}

extern "C" void kernel_launch(void* const* d_in, const int* in_sizes, int n_in,
                              void* d_out, int out_size)
{
    const float* x       = (const float*)d_in[0];
    const float* vectors = (const float*)d_in[1];
    float* out           = (float*)d_out;
    lcv_kernel<<<2048, 512>>>(x, vectors, out);
}